// round 4
// baseline (speedup 1.0000x reference)
#include <cuda_runtime.h>
#include <math.h>

// Problem constants
#define B_    128
#define T_    1024
#define H_    200
#define NJ    20          // column-slice blocks (10 hidden cols each)
#define JB    10
#define NBB   7           // batch-slice blocks (19 batches each)
#define NBLK  140         // NJ*NBB, <= 148 SMs -> all co-resident
#define NTH   256
#define WST   204         // padded smem weight row stride (floats)
#define HS    200         // smem h row stride (floats)

#define SMEM_FLOATS 28688
#define SMEM_BYTES  (SMEM_FLOATS * 4)

// ---- persistent device state (no allocations allowed) ----
__device__ float g_h0[2][B_ * H_];          // double-buffered layer-0 hidden
__device__ float g_h1[B_ * H_];             // layer-1 hidden
__device__ unsigned long long g_bar;        // monotonic barrier ticket

__device__ __forceinline__ float sigf(float v) { return 1.0f / (1.0f + __expf(-v)); }

__device__ __forceinline__ void grid_barrier() {
    __syncthreads();
    if (threadIdx.x == 0) {
        __threadfence();  // release (cumulative over the bar.sync above)
        unsigned long long t = atomicAdd(&g_bar, 1ULL);
        unsigned long long target = (t / NBLK + 1ULL) * NBLK;
        while (*((volatile unsigned long long*)&g_bar) < target) { __nanosleep(64); }
        __threadfence();  // acquire
    }
    __syncthreads();
}

__global__ void __launch_bounds__(NTH, 1)
gru_persist(const float* __restrict__ x,
            const float* __restrict__ Wih0, const float* __restrict__ Whh0,
            const float* __restrict__ bih0, const float* __restrict__ bhh0,
            const float* __restrict__ Wih1, const float* __restrict__ Whh1,
            const float* __restrict__ bih1, const float* __restrict__ bhh1,
            const float* __restrict__ Wfc,  const float* __restrict__ bfc,
            float* __restrict__ out)
{
    extern __shared__ float sm[];
    float* wA  = sm;                  // [60][WST]  rows 0-29: W_hh0 slice, 30-59: W_hh1 slice
    float* wB  = wA  + 60 * WST;      // [30][WST]  W_ih1 slice
    float* wI0 = wB  + 30 * WST;      // [30][8]    W_ih0 slice
    float* h0s = wI0 + 240;           // [20][HS]
    float* h1s = h0s + 20 * HS;       // [20][HS]
    float* ghA = h1s + 20 * HS;       // [60][20]   gh0 (0-29) / gh1 (30-59) dots
    float* gxB = ghA + 60 * 20;       // [30][20]   gx1 dots
    float* inp = gxB + 30 * 20;       // [20][8]    layer-0 inputs
    float* bi0 = inp + 160;           // [32] each, indexed by g*JB+jj
    float* bh0 = bi0 + 32;
    float* bi1 = bh0 + 32;
    float* bh1 = bi1 + 32;

    const int tid = threadIdx.x;
    const int bx  = blockIdx.x;
    const int jb  = bx % NJ, bb = bx / NJ;
    const int j0  = jb * JB;
    const int b0  = bb * 19;
    const int Bb  = min(19, B_ - b0);
    const int nbg = (Bb + 1) >> 1;

    // ---- one-time weight staging (weight-stationary) ----
    for (int idx = tid; idx < 60 * 50; idx += NTH) {
        int r = idx / 50, q = idx % 50;
        int rr = r % 30;
        int grow = (rr / JB) * H_ + j0 + (rr % JB);
        const float* src = (r < 30 ? Whh0 : Whh1) + grow * H_ + q * 4;
        *reinterpret_cast<float4*>(wA + r * WST + q * 4) =
            *reinterpret_cast<const float4*>(src);
    }
    for (int idx = tid; idx < 30 * 50; idx += NTH) {
        int r = idx / 50, q = idx % 50;
        int grow = (r / JB) * H_ + j0 + (r % JB);
        *reinterpret_cast<float4*>(wB + r * WST + q * 4) =
            *reinterpret_cast<const float4*>(Wih1 + grow * H_ + q * 4);
    }
    for (int idx = tid; idx < 240; idx += NTH) {
        int r = idx / 8, c = idx % 8;
        int grow = (r / JB) * H_ + j0 + (r % JB);
        wI0[idx] = Wih0[grow * 8 + c];
    }
    if (tid < 30) {
        int grow = (tid / JB) * H_ + j0 + (tid % JB);
        bi0[tid] = bih0[grow]; bh0[tid] = bhh0[grow];
        bi1[tid] = bih1[grow]; bh1[tid] = bhh1[grow];
    }
    // zero initial hidden state (buffer 1 is read at t=0)
    for (int idx = tid; idx < Bb * JB; idx += NTH) {
        int b = idx / JB, jj = idx % JB;
        __stcg(&g_h0[1][(b0 + b) * H_ + j0 + jj], 0.0f);
        __stcg(&g_h1[(b0 + b) * H_ + j0 + jj], 0.0f);
    }
    grid_barrier();

    for (int t = 0; t < T_; ++t) {
        const float* h0prev = g_h0[(t & 1) ^ 1];
        float*       h0cur  = g_h0[t & 1];

        // ---- FC output for step t-1 (g_h1 currently holds h1_{t-1}) ----
        if (t > 0 && bx < B_ && tid < 4) {
            const float* hp = g_h1 + bx * H_;
            const float* wp = Wfc + tid * H_;
            float a0 = 0.f, a1 = 0.f, a2 = 0.f, a3 = 0.f;
            #pragma unroll 5
            for (int k = 0; k < H_; k += 4) {
                float4 hv = __ldcg(reinterpret_cast<const float4*>(hp + k));
                float4 wv = *reinterpret_cast<const float4*>(wp + k);
                a0 = fmaf(hv.x, wv.x, a0); a1 = fmaf(hv.y, wv.y, a1);
                a2 = fmaf(hv.z, wv.z, a2); a3 = fmaf(hv.w, wv.w, a3);
            }
            out[((size_t)bx * T_ + (t - 1)) * 4 + tid] =
                tanhf((a0 + a1) + (a2 + a3) + bfc[tid]);
        }

        // ---- Phase A staging: h0_{t-1}, h1_{t-1}, layer-0 inputs ----
        for (int idx = tid; idx < Bb * 50; idx += NTH) {
            int b = idx / 50, q = (idx % 50) * 4;
            *reinterpret_cast<float4*>(h0s + b * HS + q) =
                __ldcg(reinterpret_cast<const float4*>(h0prev + (b0 + b) * H_ + q));
            *reinterpret_cast<float4*>(h1s + b * HS + q) =
                __ldcg(reinterpret_cast<const float4*>(g_h1 + (b0 + b) * H_ + q));
        }
        for (int idx = tid; idx < Bb * 8; idx += NTH) {
            int b = idx / 8, c = idx % 8;
            float v;
            if (c < 4) v = (t == 0) ? 1.0f : x[((size_t)(b0 + b) * T_ + (t - 1)) * 8 + c];
            else       v = x[((size_t)(b0 + b) * T_) * 8 + c];  // emotion = x[b,0,4:8]
            inp[b * 8 + c] = v;
        }
        __syncthreads();

        // ---- Phase A dots: gh0 (rows 0-29) and gh1 (rows 30-59), tile 5r x 2b ----
        if (tid < 12 * nbg) {
            int rg = tid % 12, bg = tid / 12;
            int bA = bg * 2, bBi = bA + 1;
            bool v2 = (bBi < Bb);
            const float* hsel = (rg < 6) ? h0s : h1s;
            const float* w0 = wA + (rg * 5) * WST;
            const float* ha = hsel + bA * HS;
            const float* hb = hsel + (v2 ? bBi : bA) * HS;
            float acc[5][2];
            #pragma unroll
            for (int i = 0; i < 5; i++) { acc[i][0] = 0.f; acc[i][1] = 0.f; }
            #pragma unroll 2
            for (int k = 0; k < H_; k += 4) {
                float4 hv0 = *reinterpret_cast<const float4*>(ha + k);
                float4 hv1 = *reinterpret_cast<const float4*>(hb + k);
                #pragma unroll
                for (int i = 0; i < 5; i++) {
                    float4 wv = *reinterpret_cast<const float4*>(w0 + i * WST + k);
                    acc[i][0] = fmaf(wv.w, hv0.w, fmaf(wv.z, hv0.z,
                                fmaf(wv.y, hv0.y, fmaf(wv.x, hv0.x, acc[i][0]))));
                    acc[i][1] = fmaf(wv.w, hv1.w, fmaf(wv.z, hv1.z,
                                fmaf(wv.y, hv1.y, fmaf(wv.x, hv1.x, acc[i][1]))));
                }
            }
            #pragma unroll
            for (int i = 0; i < 5; i++) {
                int r = rg * 5 + i;
                ghA[r * 20 + bA] = acc[i][0];
                if (v2) ghA[r * 20 + bBi] = acc[i][1];
            }
        }
        __syncthreads();

        // ---- layer-0 elementwise + write h0_t ----
        if (tid < Bb * JB) {
            int b = tid / JB, jj = tid % JB;
            float gx[3];
            #pragma unroll
            for (int g = 0; g < 3; ++g) {
                const float* w = wI0 + (g * JB + jj) * 8;
                float s = bi0[g * JB + jj];
                #pragma unroll
                for (int c = 0; c < 8; ++c) s = fmaf(w[c], inp[b * 8 + c], s);
                gx[g] = s;
            }
            float hr = ghA[(jj) * 20 + b]          + bh0[jj];
            float hz = ghA[(JB + jj) * 20 + b]     + bh0[JB + jj];
            float hn = ghA[(2 * JB + jj) * 20 + b] + bh0[2 * JB + jj];
            float r = sigf(gx[0] + hr);
            float z = sigf(gx[1] + hz);
            float n = tanhf(fmaf(r, hn, gx[2]));
            float hold = h0s[b * HS + j0 + jj];
            float hnew = fmaf(z, hold - n, n);     // (1-z)*n + z*h
            __stcg(&h0cur[(b0 + b) * H_ + j0 + jj], hnew);
        }
        grid_barrier();

        // ---- Phase B staging: h0_t ----
        for (int idx = tid; idx < Bb * 50; idx += NTH) {
            int b = idx / 50, q = (idx % 50) * 4;
            *reinterpret_cast<float4*>(h0s + b * HS + q) =
                __ldcg(reinterpret_cast<const float4*>(h0cur + (b0 + b) * H_ + q));
        }
        __syncthreads();

        // ---- Phase B dots: gx1 (rows 0-29 of W_ih1 slice), tile 3r x 2b ----
        if (tid < 10 * nbg) {
            int rg = tid % 10, bg = tid / 10;
            int bA = bg * 2, bBi = bA + 1;
            bool v2 = (bBi < Bb);
            const float* w0 = wB + (rg * 3) * WST;
            const float* ha = h0s + bA * HS;
            const float* hb = h0s + (v2 ? bBi : bA) * HS;
            float acc[3][2];
            #pragma unroll
            for (int i = 0; i < 3; i++) { acc[i][0] = 0.f; acc[i][1] = 0.f; }
            #pragma unroll 2
            for (int k = 0; k < H_; k += 4) {
                float4 hv0 = *reinterpret_cast<const float4*>(ha + k);
                float4 hv1 = *reinterpret_cast<const float4*>(hb + k);
                #pragma unroll
                for (int i = 0; i < 3; i++) {
                    float4 wv = *reinterpret_cast<const float4*>(w0 + i * WST + k);
                    acc[i][0] = fmaf(wv.w, hv0.w, fmaf(wv.z, hv0.z,
                                fmaf(wv.y, hv0.y, fmaf(wv.x, hv0.x, acc[i][0]))));
                    acc[i][1] = fmaf(wv.w, hv1.w, fmaf(wv.z, hv1.z,
                                fmaf(wv.y, hv1.y, fmaf(wv.x, hv1.x, acc[i][1]))));
                }
            }
            #pragma unroll
            for (int i = 0; i < 3; i++) {
                int r = rg * 3 + i;
                gxB[r * 20 + bA] = acc[i][0];
                if (v2) gxB[r * 20 + bBi] = acc[i][1];
            }
        }
        __syncthreads();

        // ---- layer-1 elementwise + write h1_t ----
        if (tid < Bb * JB) {
            int b = tid / JB, jj = tid % JB;
            float ir  = gxB[(jj) * 20 + b]          + bi1[jj];
            float iz  = gxB[(JB + jj) * 20 + b]     + bi1[JB + jj];
            float inn = gxB[(2 * JB + jj) * 20 + b] + bi1[2 * JB + jj];
            float hr = ghA[(30 + jj) * 20 + b]          + bh1[jj];
            float hz = ghA[(30 + JB + jj) * 20 + b]     + bh1[JB + jj];
            float hn = ghA[(30 + 2 * JB + jj) * 20 + b] + bh1[2 * JB + jj];
            float r = sigf(ir + hr);
            float z = sigf(iz + hz);
            float n = tanhf(fmaf(r, hn, inn));
            float hold = h1s[b * HS + j0 + jj];
            float hnew = fmaf(z, hold - n, n);
            __stcg(&g_h1[(b0 + b) * H_ + j0 + jj], hnew);
        }
        grid_barrier();
    }

    // ---- final FC for t = T-1 ----
    if (bx < B_ && tid < 4) {
        const float* hp = g_h1 + bx * H_;
        const float* wp = Wfc + tid * H_;
        float a0 = 0.f, a1 = 0.f, a2 = 0.f, a3 = 0.f;
        #pragma unroll 5
        for (int k = 0; k < H_; k += 4) {
            float4 hv = __ldcg(reinterpret_cast<const float4*>(hp + k));
            float4 wv = *reinterpret_cast<const float4*>(wp + k);
            a0 = fmaf(hv.x, wv.x, a0); a1 = fmaf(hv.y, wv.y, a1);
            a2 = fmaf(hv.z, wv.z, a2); a3 = fmaf(hv.w, wv.w, a3);
        }
        out[((size_t)bx * T_ + (T_ - 1)) * 4 + tid] =
            tanhf((a0 + a1) + (a2 + a3) + bfc[tid]);
    }
}

extern "C" void kernel_launch(void* const* d_in, const int* in_sizes, int n_in,
                              void* d_out, int out_size) {
    (void)in_sizes; (void)n_in; (void)out_size;
    cudaFuncSetAttribute(gru_persist, cudaFuncAttributeMaxDynamicSharedMemorySize,
                         SMEM_BYTES);
    gru_persist<<<NBLK, NTH, SMEM_BYTES>>>(
        (const float*)d_in[0],                      // x
        (const float*)d_in[1], (const float*)d_in[2],   // W_ih0, W_hh0
        (const float*)d_in[3], (const float*)d_in[4],   // b_ih0, b_hh0
        (const float*)d_in[5], (const float*)d_in[6],   // W_ih1, W_hh1
        (const float*)d_in[7], (const float*)d_in[8],   // b_ih1, b_hh1
        (const float*)d_in[9], (const float*)d_in[10],  // W_fc, b_fc
        (float*)d_out);
}

// round 5
// speedup vs baseline: 1.1905x; 1.1905x over previous
#include <cuda_runtime.h>
#include <math.h>

// Problem constants
#define B_    128
#define T_    1024
#define H_    200
#define NJ    20          // column-slice blocks (10 hidden cols each)
#define JB    10
#define NBB   7           // batch-slice blocks (19 batches each)
#define NBLK  140         // NJ*NBB, <= 148 SMs -> all co-resident
#define NTH   256
#define WST   204         // padded smem weight row stride (floats)
#define HS    204         // padded smem h row stride (floats) -> conflict-free lane-per-batch

// smem layout (floats)
#define OFF_WA   0                       // [60][WST] rows 0-29 W_hh0 slice, 30-59 W_hh1 slice
#define OFF_WB   (OFF_WA  + 60*WST)      // [30][WST] W_ih1 slice
#define OFF_WI0  (OFF_WB  + 30*WST)      // [30][8]   W_ih0 slice
#define OFF_WFC  (OFF_WI0 + 240)         // [4][200]  W_fc (full)
#define OFF_H0S  (OFF_WFC + 800)         // [20][HS]
#define OFF_H1S  (OFF_H0S + 20*HS)       // [20][HS]
#define OFF_GHA  (OFF_H1S + 20*HS)       // [60][20]  gh0 (0-29) / gh1 (30-59)
#define OFF_GXB  (OFF_GHA + 1200)        // [30][20]  gx1
#define OFF_INP  (OFF_GXB + 600)         // [20][8]
#define OFF_BI0  (OFF_INP + 160)
#define OFF_BH0  (OFF_BI0 + 32)
#define OFF_BI1  (OFF_BH0 + 32)
#define OFF_BH1  (OFF_BI1 + 32)
#define OFF_BFC  (OFF_BH1 + 32)
#define SMEM_FLOATS (OFF_BFC + 4)
#define SMEM_BYTES  (SMEM_FLOATS * 4)

// ---- persistent device state (no allocations allowed) ----
__device__ float g_h0[2][B_ * H_];          // double-buffered layer-0 hidden
__device__ float g_h1[B_ * H_];             // layer-1 hidden
__device__ unsigned long long g_bar;        // monotonic barrier ticket

__device__ __forceinline__ float sigf(float v) { return 1.0f / (1.0f + __expf(-v)); }

// packed dual-FMA: d.lo += a.lo*b.lo ; d.hi += a.hi*b.hi
__device__ __forceinline__ void ffma2(unsigned long long &d,
                                      unsigned long long a, unsigned long long b) {
    asm("fma.rn.f32x2 %0, %1, %2, %0;" : "+l"(d) : "l"(a), "l"(b));
}
__device__ __forceinline__ float hsum2(unsigned long long a) {
    unsigned lo, hi;
    asm("mov.b64 {%0,%1}, %2;" : "=r"(lo), "=r"(hi) : "l"(a));
    return __uint_as_float(lo) + __uint_as_float(hi);
}

__device__ __forceinline__ void grid_barrier() {
    __syncthreads();
    if (threadIdx.x == 0) {
        __threadfence();  // release
        unsigned long long t = atomicAdd(&g_bar, 1ULL);
        unsigned long long target = (t / NBLK + 1ULL) * NBLK;
        while (*((volatile unsigned long long*)&g_bar) < target) { __nanosleep(32); }
        __threadfence();  // acquire
    }
    __syncthreads();
}

__global__ void __launch_bounds__(NTH, 1)
gru_persist(const float* __restrict__ x,
            const float* __restrict__ Wih0, const float* __restrict__ Whh0,
            const float* __restrict__ bih0, const float* __restrict__ bhh0,
            const float* __restrict__ Wih1, const float* __restrict__ Whh1,
            const float* __restrict__ bih1, const float* __restrict__ bhh1,
            const float* __restrict__ Wfc,  const float* __restrict__ bfc,
            float* __restrict__ out)
{
    extern __shared__ float sm[];
    float* wA   = sm + OFF_WA;
    float* wB   = sm + OFF_WB;
    float* wI0  = sm + OFF_WI0;
    float* wFcS = sm + OFF_WFC;
    float* h0s  = sm + OFF_H0S;
    float* h1s  = sm + OFF_H1S;
    float* ghA  = sm + OFF_GHA;
    float* gxB  = sm + OFF_GXB;
    float* inp  = sm + OFF_INP;
    float* bi0  = sm + OFF_BI0;
    float* bh0  = sm + OFF_BH0;
    float* bi1  = sm + OFF_BI1;
    float* bh1  = sm + OFF_BH1;
    float* bfcS = sm + OFF_BFC;

    const int tid = threadIdx.x;
    const int bx  = blockIdx.x;
    const int jb  = bx % NJ, bb = bx / NJ;
    const int j0  = jb * JB;
    const int b0  = bb * 19;
    const int Bb  = min(19, B_ - b0);

    // ---- one-time weight staging (weight-stationary) ----
    for (int idx = tid; idx < 60 * 50; idx += NTH) {
        int r = idx / 50, q = idx % 50;
        int rr = r % 30;
        int grow = (rr / JB) * H_ + j0 + (rr % JB);
        const float* src = (r < 30 ? Whh0 : Whh1) + grow * H_ + q * 4;
        *reinterpret_cast<float4*>(wA + r * WST + q * 4) =
            *reinterpret_cast<const float4*>(src);
    }
    for (int idx = tid; idx < 30 * 50; idx += NTH) {
        int r = idx / 50, q = idx % 50;
        int grow = (r / JB) * H_ + j0 + (r % JB);
        *reinterpret_cast<float4*>(wB + r * WST + q * 4) =
            *reinterpret_cast<const float4*>(Wih1 + grow * H_ + q * 4);
    }
    for (int idx = tid; idx < 240; idx += NTH) {
        int r = idx / 8, c = idx % 8;
        int grow = (r / JB) * H_ + j0 + (r % JB);
        wI0[idx] = Wih0[grow * 8 + c];
    }
    for (int idx = tid; idx < 800; idx += NTH) wFcS[idx] = Wfc[idx];
    if (tid < 30) {
        int grow = (tid / JB) * H_ + j0 + (tid % JB);
        bi0[tid] = bih0[grow]; bh0[tid] = bhh0[grow];
        bi1[tid] = bih1[grow]; bh1[tid] = bhh1[grow];
    }
    if (tid < 4) bfcS[tid] = bfc[tid];
    // zero smem h tiles (padding rows read by inactive lanes)
    for (int idx = tid; idx < 20 * HS; idx += NTH) { h0s[idx] = 0.f; h1s[idx] = 0.f; }
    // zero initial hidden state (buffer 1 is read at t=0)
    for (int idx = tid; idx < Bb * JB; idx += NTH) {
        int b = idx / JB, jj = idx % JB;
        __stcg(&g_h0[1][(b0 + b) * H_ + j0 + jj], 0.0f);
        __stcg(&g_h1[(b0 + b) * H_ + j0 + jj], 0.0f);
    }
    grid_barrier();

    for (int t = 0; t < T_; ++t) {
        const float* h0prev = g_h0[(t & 1) ^ 1];
        float*       h0cur  = g_h0[t & 1];

        // ---- Phase A staging: h0_{t-1}, h1_{t-1}, layer-0 inputs ----
        for (int idx = tid; idx < Bb * 50; idx += NTH) {
            int b = idx / 50, q = (idx % 50) * 4;
            *reinterpret_cast<float4*>(h0s + b * HS + q) =
                __ldcg(reinterpret_cast<const float4*>(h0prev + (b0 + b) * H_ + q));
            *reinterpret_cast<float4*>(h1s + b * HS + q) =
                __ldcg(reinterpret_cast<const float4*>(g_h1 + (b0 + b) * H_ + q));
        }
        for (int idx = tid; idx < Bb * 8; idx += NTH) {
            int b = idx / 8, c = idx % 8;
            float v;
            if (c < 4) v = (t == 0) ? 1.0f : x[((size_t)(b0 + b) * T_ + (t - 1)) * 8 + c];
            else       v = x[((size_t)(b0 + b) * T_) * 8 + c];  // emotion = x[b,0,4:8]
            inp[b * 8 + c] = v;
        }
        __syncthreads();

        // ---- Phase A dots: gh0 (rows 0-29, vs h0) and gh1 (rows 30-59, vs h1) ----
        // warp lanes = batch -> weight loads broadcast within warp
        if (tid < 240) {
            const int rg = tid / 20, b = tid % 20;
            const float* hrow = ((rg < 6) ? h0s : h1s) + b * HS;
            const float* w0 = wA + (rg * 5) * WST;
            unsigned long long a0[5], a1[5];
            #pragma unroll
            for (int i = 0; i < 5; i++) { a0[i] = 0ULL; a1[i] = 0ULL; }
            #pragma unroll 2
            for (int k = 0; k < H_; k += 4) {
                ulonglong2 h2 = *reinterpret_cast<const ulonglong2*>(hrow + k);
                #pragma unroll
                for (int i = 0; i < 5; i++) {
                    ulonglong2 w2 = *reinterpret_cast<const ulonglong2*>(w0 + i * WST + k);
                    ffma2(a0[i], w2.x, h2.x);
                    ffma2(a1[i], w2.y, h2.y);
                }
            }
            if (b < Bb) {
                #pragma unroll
                for (int i = 0; i < 5; i++)
                    ghA[(rg * 5 + i) * 20 + b] = hsum2(a0[i]) + hsum2(a1[i]);
            }
        }
        __syncthreads();

        // ---- layer-0 elementwise + write h0_t ----
        if (tid < Bb * JB) {
            int b = tid / JB, jj = tid % JB;
            float gx[3];
            #pragma unroll
            for (int g = 0; g < 3; ++g) {
                const float* w = wI0 + (g * JB + jj) * 8;
                float s = bi0[g * JB + jj];
                #pragma unroll
                for (int c = 0; c < 8; ++c) s = fmaf(w[c], inp[b * 8 + c], s);
                gx[g] = s;
            }
            float hr = ghA[(jj) * 20 + b]          + bh0[jj];
            float hz = ghA[(JB + jj) * 20 + b]     + bh0[JB + jj];
            float hn = ghA[(2 * JB + jj) * 20 + b] + bh0[2 * JB + jj];
            float r = sigf(gx[0] + hr);
            float z = sigf(gx[1] + hz);
            float n = tanhf(fmaf(r, hn, gx[2]));
            float hold = h0s[b * HS + j0 + jj];
            float hnew = fmaf(z, hold - n, n);     // (1-z)*n + z*h
            __stcg(&h0cur[(b0 + b) * H_ + j0 + jj], hnew);
        }
        grid_barrier();

        // ---- Phase B staging: h0_t ----
        for (int idx = tid; idx < Bb * 50; idx += NTH) {
            int b = idx / 50, q = (idx % 50) * 4;
            *reinterpret_cast<float4*>(h0s + b * HS + q) =
                __ldcg(reinterpret_cast<const float4*>(h0cur + (b0 + b) * H_ + q));
        }
        __syncthreads();

        // ---- Phase B dots: gx1 (warps 0-3) | FC for t-1 (warps 4-7, jb==0) ----
        if (tid < 120) {
            const int rg = tid / 20, b = tid % 20;
            const float* hrow = h0s + b * HS;
            const float* w0 = wB + (rg * 5) * WST;
            unsigned long long a0[5], a1[5];
            #pragma unroll
            for (int i = 0; i < 5; i++) { a0[i] = 0ULL; a1[i] = 0ULL; }
            #pragma unroll 2
            for (int k = 0; k < H_; k += 4) {
                ulonglong2 h2 = *reinterpret_cast<const ulonglong2*>(hrow + k);
                #pragma unroll
                for (int i = 0; i < 5; i++) {
                    ulonglong2 w2 = *reinterpret_cast<const ulonglong2*>(w0 + i * WST + k);
                    ffma2(a0[i], w2.x, h2.x);
                    ffma2(a1[i], w2.y, h2.y);
                }
            }
            if (b < Bb) {
                #pragma unroll
                for (int i = 0; i < 5; i++)
                    gxB[(rg * 5 + i) * 20 + b] = hsum2(a0[i]) + hsum2(a1[i]);
            }
        } else if (jb == 0 && t > 0 && tid >= 128) {
            // FC output for step t-1: h1s still holds h1_{t-1} (smem-resident)
            int d = tid - 128;
            if (d < Bb * 4) {
                int b = d >> 2, o = d & 3;
                const float* hrow = h1s + b * HS;
                const float* wrow = wFcS + o * 200;
                unsigned long long a0 = 0ULL, a1 = 0ULL;
                #pragma unroll 2
                for (int k = 0; k < H_; k += 4) {
                    ulonglong2 h2 = *reinterpret_cast<const ulonglong2*>(hrow + k);
                    ulonglong2 w2 = *reinterpret_cast<const ulonglong2*>(wrow + k);
                    ffma2(a0, w2.x, h2.x);
                    ffma2(a1, w2.y, h2.y);
                }
                out[((size_t)(b0 + b) * T_ + (t - 1)) * 4 + o] =
                    tanhf(hsum2(a0) + hsum2(a1) + bfcS[o]);
            }
        }
        __syncthreads();

        // ---- layer-1 elementwise + write h1_t ----
        if (tid < Bb * JB) {
            int b = tid / JB, jj = tid % JB;
            float ir  = gxB[(jj) * 20 + b]          + bi1[jj];
            float iz  = gxB[(JB + jj) * 20 + b]     + bi1[JB + jj];
            float inn = gxB[(2 * JB + jj) * 20 + b] + bi1[2 * JB + jj];
            float hr = ghA[(30 + jj) * 20 + b]          + bh1[jj];
            float hz = ghA[(30 + JB + jj) * 20 + b]     + bh1[JB + jj];
            float hn = ghA[(30 + 2 * JB + jj) * 20 + b] + bh1[2 * JB + jj];
            float r = sigf(ir + hr);
            float z = sigf(iz + hz);
            float n = tanhf(fmaf(r, hn, inn));
            float hold = h1s[b * HS + j0 + jj];
            float hnew = fmaf(z, hold - n, n);
            __stcg(&g_h1[(b0 + b) * H_ + j0 + jj], hnew);
        }
        grid_barrier();
    }

    // ---- final FC for t = T-1 (jb==0 blocks; g_h1 holds h1_{T-1}) ----
    if (jb == 0) {
        for (int idx = tid; idx < Bb * 50; idx += NTH) {
            int b = idx / 50, q = (idx % 50) * 4;
            *reinterpret_cast<float4*>(h1s + b * HS + q) =
                __ldcg(reinterpret_cast<const float4*>(g_h1 + (b0 + b) * H_ + q));
        }
        __syncthreads();
        if (tid < Bb * 4) {
            int b = tid >> 2, o = tid & 3;
            const float* hrow = h1s + b * HS;
            const float* wrow = wFcS + o * 200;
            unsigned long long a0 = 0ULL, a1 = 0ULL;
            #pragma unroll 2
            for (int k = 0; k < H_; k += 4) {
                ulonglong2 h2 = *reinterpret_cast<const ulonglong2*>(hrow + k);
                ulonglong2 w2 = *reinterpret_cast<const ulonglong2*>(wrow + k);
                ffma2(a0, w2.x, h2.x);
                ffma2(a1, w2.y, h2.y);
            }
            out[((size_t)(b0 + b) * T_ + (T_ - 1)) * 4 + o] =
                tanhf(hsum2(a0) + hsum2(a1) + bfcS[o]);
        }
    }
}

extern "C" void kernel_launch(void* const* d_in, const int* in_sizes, int n_in,
                              void* d_out, int out_size) {
    (void)in_sizes; (void)n_in; (void)out_size;
    cudaFuncSetAttribute(gru_persist, cudaFuncAttributeMaxDynamicSharedMemorySize,
                         SMEM_BYTES);
    gru_persist<<<NBLK, NTH, SMEM_BYTES>>>(
        (const float*)d_in[0],                          // x
        (const float*)d_in[1], (const float*)d_in[2],   // W_ih0, W_hh0
        (const float*)d_in[3], (const float*)d_in[4],   // b_ih0, b_hh0
        (const float*)d_in[5], (const float*)d_in[6],   // W_ih1, W_hh1
        (const float*)d_in[7], (const float*)d_in[8],   // b_ih1, b_hh1
        (const float*)d_in[9], (const float*)d_in[10],  // W_fc, b_fc
        (float*)d_out);
}